// round 4
// baseline (speedup 1.0000x reference)
#include <cuda_runtime.h>
#include <cstdint>

#define BB 8
#define NN 256
#define FF 64
#define ROWS (BB * NN)          // 2048
#define W_ELEMS ((size_t)BB * NN * NN * FF)  // 33,554,432

#define TILE_J 64
#define TILE_BYTES (TILE_J * FF * 4)   // 16384
#define NTILES 4                       // 4 x 16KB = one full W row (64KB)

// Scratch (allocation-free rule: __device__ globals), 16B aligned for float4.
__device__ __align__(16) float g_x1[ROWS * FF];  // relu MLP(n) of x
__device__ __align__(16) float g_s[ROWS * FF];   // relu MLP(s) of x

// ---------------------------------------------------------------------------
// PTX helpers
// ---------------------------------------------------------------------------
__device__ __forceinline__ uint32_t s2u(const void* p) {
    return (uint32_t)__cvta_generic_to_shared(p);
}
__device__ __forceinline__ void mbar_init(uint32_t mbar, uint32_t count) {
    asm volatile("mbarrier.init.shared.b64 [%0], %1;" :: "r"(mbar), "r"(count) : "memory");
}
__device__ __forceinline__ void mbar_expect_tx(uint32_t mbar, uint32_t bytes) {
    asm volatile("mbarrier.arrive.expect_tx.shared.b64 _, [%0], %1;"
                 :: "r"(mbar), "r"(bytes) : "memory");
}
__device__ __forceinline__ void mbar_wait(uint32_t mbar, uint32_t parity) {
    uint32_t done;
    asm volatile(
        "{\n\t.reg .pred p;\n\t"
        "mbarrier.try_wait.parity.acquire.cta.shared::cta.b64 p, [%1], %2;\n\t"
        "selp.b32 %0, 1, 0, p;\n\t}"
        : "=r"(done) : "r"(mbar), "r"(parity) : "memory");
    while (!done) {
        asm volatile(
            "{\n\t.reg .pred p;\n\t"
            "mbarrier.try_wait.parity.acquire.cta.shared::cta.b64 p, [%1], %2, 0x989680;\n\t"
            "selp.b32 %0, 1, 0, p;\n\t}"
            : "=r"(done) : "r"(mbar), "r"(parity) : "memory");
    }
}
__device__ __forceinline__ void bulk_g2s(uint32_t dst_smem, const void* src,
                                         uint32_t bytes, uint32_t mbar) {
    asm volatile(
        "cp.async.bulk.shared::cluster.global.mbarrier::complete_tx::bytes "
        "[%0], [%1], %2, [%3];"
        :: "r"(dst_smem), "l"(src), "r"(bytes), "r"(mbar) : "memory");
}
__device__ __forceinline__ void bulk_s2g(void* dst, uint32_t src_smem, uint32_t bytes) {
    asm volatile("cp.async.bulk.global.shared::cta.bulk_group [%0], [%1], %2;"
                 :: "l"(dst), "r"(src_smem), "r"(bytes) : "memory");
}
__device__ __forceinline__ void bulk_commit() {
    asm volatile("cp.async.bulk.commit_group;" ::: "memory");
}
__device__ __forceinline__ void bulk_wait_all() {
    asm volatile("cp.async.bulk.wait_group 0;" ::: "memory");
}

// ---------------------------------------------------------------------------
// Kernel 1: both MLPs. 128 blocks x 256 threads; 16 rows per block.
// Thread (g,e) computes output feature e for rows 4g..4g+3.
// Calls cudaTriggerProgrammaticLaunchCompletion() at entry so the PDL
// secondary (agg_kernel) can launch and run its W-load prologue concurrently.
// ---------------------------------------------------------------------------
__global__ __launch_bounds__(256) void mlp_kernel(
    const float* __restrict__ x,
    const float* __restrict__ nw1, const float* __restrict__ nb1,
    const float* __restrict__ nw2, const float* __restrict__ nb2,
    const float* __restrict__ sw1, const float* __restrict__ sb1,
    const float* __restrict__ sw2, const float* __restrict__ sb2)
{
    cudaTriggerProgrammaticLaunchCompletion();

    __shared__ float s_w1[2][FF * FF];
    __shared__ float s_w2[2][FF * FF];
    __shared__ float s_b1[2][FF], s_b2[2][FF];
    __shared__ float sxT[FF][17];   // [k][row], padded
    __shared__ float shT[FF][17];   // hidden transposed

    int tid = threadIdx.x;
    int e = tid & 63;
    int g = tid >> 6;        // row quad 0..3

    for (int i = tid; i < FF * FF / 4; i += 256) {
        ((float4*)s_w1[0])[i] = ((const float4*)nw1)[i];
        ((float4*)s_w2[0])[i] = ((const float4*)nw2)[i];
        ((float4*)s_w1[1])[i] = ((const float4*)sw1)[i];
        ((float4*)s_w2[1])[i] = ((const float4*)sw2)[i];
    }
    if (tid < FF) {
        s_b1[0][tid] = nb1[tid];
        s_b2[0][tid] = nb2[tid];
        s_b1[1][tid] = sb1[tid];
        s_b2[1][tid] = sb2[tid];
    }

    int base = blockIdx.x * 16;     // 16 rows per block
    {
        float4 v = ((const float4*)(x + (size_t)base * FF))[tid];
        int r  = (tid * 4) / FF;    // row 0..15
        int k0 = (tid * 4) % FF;
        sxT[k0 + 0][r] = v.x;
        sxT[k0 + 1][r] = v.y;
        sxT[k0 + 2][r] = v.z;
        sxT[k0 + 3][r] = v.w;
    }
    __syncthreads();

    for (int p = 0; p < 2; p++) {   // p=0: n-MLP -> g_x1 ; p=1: s-MLP -> g_s
        float a0 = s_b1[p][e], a1 = a0, a2 = a0, a3 = a0;
        #pragma unroll
        for (int k = 0; k < FF; k++) {
            float w = s_w1[p][k * FF + e];
            a0 = fmaf(w, sxT[k][4 * g + 0], a0);
            a1 = fmaf(w, sxT[k][4 * g + 1], a1);
            a2 = fmaf(w, sxT[k][4 * g + 2], a2);
            a3 = fmaf(w, sxT[k][4 * g + 3], a3);
        }
        shT[e][4 * g + 0] = fmaxf(a0, 0.f);
        shT[e][4 * g + 1] = fmaxf(a1, 0.f);
        shT[e][4 * g + 2] = fmaxf(a2, 0.f);
        shT[e][4 * g + 3] = fmaxf(a3, 0.f);
        __syncthreads();

        float c0 = s_b2[p][e], c1 = c0, c2 = c0, c3 = c0;
        #pragma unroll
        for (int k = 0; k < FF; k++) {
            float w = s_w2[p][k * FF + e];
            c0 = fmaf(w, shT[k][4 * g + 0], c0);
            c1 = fmaf(w, shT[k][4 * g + 1], c1);
            c2 = fmaf(w, shT[k][4 * g + 2], c2);
            c3 = fmaf(w, shT[k][4 * g + 3], c3);
        }
        float* out = p ? g_s : g_x1;
        out[(size_t)(base + 4 * g + 0) * FF + e] = fmaxf(c0, 0.f);
        out[(size_t)(base + 4 * g + 1) * FF + e] = fmaxf(c1, 0.f);
        out[(size_t)(base + 4 * g + 2) * FF + e] = fmaxf(c2, 0.f);
        out[(size_t)(base + 4 * g + 3) * FF + e] = fmaxf(c3, 0.f);
        __syncthreads();    // protect shT before p=1
    }
}

// ---------------------------------------------------------------------------
// Kernel 2: fused L1-normalize + einsum + W copy + add s-MLP.
// One block per (b,i). The full 64KB W row sits in 4 dynamic-smem tiles.
// All 4 TMA loads are issued up-front (each stage written exactly once: no
// ring reuse -> loads are NEVER gated on store drains). Per tile: as its
// mbarrier completes, the TMA store of that tile is issued immediately (load
// and store both touch the tile via the async proxy only; compute merely
// reads it -> no fence / no per-tile syncthreads), then the einsum partial
// is accumulated. One wait_group 0 at block end.
// PDL: cudaGridDependencySynchronize() is called only after the W loads are
// in flight, so the memory prologue overlaps mlp_kernel.
// ---------------------------------------------------------------------------
__global__ __launch_bounds__(256) void agg_kernel(
    const float* __restrict__ A,
    const char* __restrict__ W,
    char* __restrict__ outW,
    float* __restrict__ outX2)
{
    extern __shared__ __align__(128) char tiles[];   // NTILES * TILE_BYTES
    __shared__ float sAn[NN];
    __shared__ float4 red[256];
    __shared__ float warp_s[8];
    __shared__ float sden;
    __shared__ __align__(8) unsigned long long mbar_st[NTILES];

    int bi = blockIdx.x;          // b*256 + i
    int b  = bi >> 8;
    int tid = threadIdx.x;

    // L1 denom over the A row (each thread owns one j).
    float a = A[(size_t)bi * NN + tid];
    float v = fabsf(a);
    #pragma unroll
    for (int off = 16; off; off >>= 1) v += __shfl_xor_sync(0xffffffffu, v, off);
    if ((tid & 31) == 0) warp_s[tid >> 5] = v;
    if (tid < NTILES) mbar_init(s2u(&mbar_st[tid]), 1);
    __syncthreads();   // mbar init visible; warp_s ready

    const char* Wrow = W    + (size_t)bi * (NN * FF * 4);
    char*       Orow = outW + (size_t)bi * (NN * FF * 4);

    if (tid == 0) {
        float t = 0.f;
        #pragma unroll
        for (int w = 0; w < 8; w++) t += warp_s[w];
        sden = fmaxf(t, 1e-12f);
        // Kick off ALL W-row tile loads now.
        #pragma unroll
        for (int t4 = 0; t4 < NTILES; t4++) {
            uint32_t mb = s2u(&mbar_st[t4]);
            mbar_expect_tx(mb, TILE_BYTES);
            bulk_g2s(s2u(tiles + t4 * TILE_BYTES),
                     Wrow + (size_t)t4 * TILE_BYTES, TILE_BYTES, mb);
        }
    }
    __syncthreads();
    sAn[tid] = a / sden;
    __syncthreads();

    // Wait for mlp_kernel's g_x1 / g_s to be visible (PDL). The W TMA loads
    // above are already streaming while we wait.
    cudaGridDependencySynchronize();

    const float4* x1b = ((const float4*)g_x1) + (size_t)b * (NN * 16);
    int e4 = tid & 15;    // float4 lane (features e4*4 .. e4*4+3)
    int jg = tid >> 4;    // j group 0..15 within tile

    float4 acc = make_float4(0.f, 0.f, 0.f, 0.f);

    #pragma unroll
    for (int t = 0; t < NTILES; t++) {
        mbar_wait(s2u(&mbar_st[t]), 0);   // tile t resident
        if (tid == 0) {                    // copy-out of tile t starts now
            bulk_s2g(Orow + (size_t)t * TILE_BYTES,
                     s2u(tiles + t * TILE_BYTES), TILE_BYTES);
            bulk_commit();
        }
        const float4* Wt = (const float4*)(tiles + t * TILE_BYTES);
        #pragma unroll
        for (int k = 0; k < TILE_J / 16; k++) {
            int jl = jg + 16 * k;          // j within tile
            int j  = t * TILE_J + jl;
            float4 w   = Wt[jl * 16 + e4];
            float4 x1v = x1b[j * 16 + e4];
            float  tt  = sAn[j];
            acc.x = fmaf(tt * w.x, x1v.x, acc.x);
            acc.y = fmaf(tt * w.y, x1v.y, acc.y);
            acc.z = fmaf(tt * w.z, x1v.z, acc.z);
            acc.w = fmaf(tt * w.w, x1v.w, acc.w);
        }
    }

    red[tid] = acc;
    __syncthreads();

    if (tid < 16) {
        float4 r = red[tid];
        #pragma unroll
        for (int k = 1; k < 16; k++) {
            float4 t = red[k * 16 + tid];
            r.x += t.x; r.y += t.y; r.z += t.z; r.w += t.w;
        }
        float4 sv = ((const float4*)g_s)[bi * 16 + tid];
        r.x += sv.x; r.y += sv.y; r.z += sv.z; r.w += sv.w;
        ((float4*)outX2)[bi * 16 + tid] = r;
    }

    if (tid == 0) bulk_wait_all();   // drain all 4 W-tile stores
}

// ---------------------------------------------------------------------------
extern "C" void kernel_launch(void* const* d_in, const int* in_sizes, int n_in,
                              void* d_out, int out_size)
{
    const float* A   = (const float*)d_in[0];
    const float* W   = (const float*)d_in[1];
    const float* x   = (const float*)d_in[2];
    const float* nw1 = (const float*)d_in[3];
    const float* nb1 = (const float*)d_in[4];
    const float* nw2 = (const float*)d_in[5];
    const float* nb2 = (const float*)d_in[6];
    const float* sw1 = (const float*)d_in[7];
    const float* sb1 = (const float*)d_in[8];
    const float* sw2 = (const float*)d_in[9];
    const float* sb2 = (const float*)d_in[10];

    float* outW  = (float*)d_out;            // W passthrough, 33,554,432 floats
    float* outX2 = (float*)d_out + W_ELEMS;  // x2, 131,072 floats

    static bool attr_set = false;
    if (!attr_set) {
        cudaFuncSetAttribute(agg_kernel,
                             cudaFuncAttributeMaxDynamicSharedMemorySize,
                             NTILES * TILE_BYTES);
        attr_set = true;
    }

    // Primary: mlp (triggers PDL completion at entry).
    mlp_kernel<<<128, 256>>>(x, nw1, nb1, nw2, nb2, sw1, sb1, sw2, sb2);

    // Secondary: agg with programmatic stream serialization (overlaps its
    // W-load prologue with mlp, syncs on g_x1/g_s via GridDependencySync).
    cudaLaunchConfig_t cfg = {};
    cfg.gridDim = dim3(ROWS);
    cfg.blockDim = dim3(256);
    cfg.dynamicSmemBytes = NTILES * TILE_BYTES;
    cfg.stream = 0;
    cudaLaunchAttribute attrs[1];
    attrs[0].id = cudaLaunchAttributeProgrammaticStreamSerialization;
    attrs[0].val.programmaticStreamSerializationAllowed = 1;
    cfg.attrs = attrs;
    cfg.numAttrs = 1;
    cudaLaunchKernelEx(&cfg, agg_kernel, A, (const char*)W, (char*)outW, outX2);
}

// round 5
// speedup vs baseline: 1.0457x; 1.0457x over previous
#include <cuda_runtime.h>
#include <cstdint>

#define BB 8
#define NN 256
#define FF 64
#define ROWS (BB * NN)          // 2048
#define W_ELEMS ((size_t)BB * NN * NN * FF)  // 33,554,432

#define TILE_J 64
#define TILE_BYTES (TILE_J * FF * 4)   // 16384
#define NTILES (NN / TILE_J)           // 4

// Scratch (allocation-free rule: __device__ globals), 16B aligned for float4.
__device__ __align__(16) float g_x1[ROWS * FF];  // relu MLP(n) of x
__device__ __align__(16) float g_s[ROWS * FF];   // relu MLP(s) of x

// ---------------------------------------------------------------------------
// PTX helpers
// ---------------------------------------------------------------------------
__device__ __forceinline__ uint32_t s2u(const void* p) {
    return (uint32_t)__cvta_generic_to_shared(p);
}
__device__ __forceinline__ void mbar_init(uint32_t mbar, uint32_t count) {
    asm volatile("mbarrier.init.shared.b64 [%0], %1;" :: "r"(mbar), "r"(count) : "memory");
}
__device__ __forceinline__ void mbar_expect_tx(uint32_t mbar, uint32_t bytes) {
    asm volatile("mbarrier.arrive.expect_tx.shared.b64 _, [%0], %1;"
                 :: "r"(mbar), "r"(bytes) : "memory");
}
__device__ __forceinline__ void mbar_wait(uint32_t mbar, uint32_t parity) {
    uint32_t done;
    asm volatile(
        "{\n\t.reg .pred p;\n\t"
        "mbarrier.try_wait.parity.acquire.cta.shared::cta.b64 p, [%1], %2;\n\t"
        "selp.b32 %0, 1, 0, p;\n\t}"
        : "=r"(done) : "r"(mbar), "r"(parity) : "memory");
    while (!done) {
        asm volatile(
            "{\n\t.reg .pred p;\n\t"
            "mbarrier.try_wait.parity.acquire.cta.shared::cta.b64 p, [%1], %2, 0x989680;\n\t"
            "selp.b32 %0, 1, 0, p;\n\t}"
            : "=r"(done) : "r"(mbar), "r"(parity) : "memory");
    }
}
__device__ __forceinline__ void bulk_g2s(uint32_t dst_smem, const void* src,
                                         uint32_t bytes, uint32_t mbar) {
    asm volatile(
        "cp.async.bulk.shared::cluster.global.mbarrier::complete_tx::bytes "
        "[%0], [%1], %2, [%3];"
        :: "r"(dst_smem), "l"(src), "r"(bytes), "r"(mbar) : "memory");
}
__device__ __forceinline__ void bulk_s2g(void* dst, uint32_t src_smem, uint32_t bytes) {
    asm volatile("cp.async.bulk.global.shared::cta.bulk_group [%0], [%1], %2;"
                 :: "l"(dst), "r"(src_smem), "r"(bytes) : "memory");
}
__device__ __forceinline__ void bulk_commit() {
    asm volatile("cp.async.bulk.commit_group;" ::: "memory");
}
// Wait until outstanding bulk-store groups have READ their smem source
// (stage reusable) — does NOT wait for the gmem write to land.
__device__ __forceinline__ void bulk_wait_read0() {
    asm volatile("cp.async.bulk.wait_group.read 0;" ::: "memory");
}
__device__ __forceinline__ void bulk_wait_all() {
    asm volatile("cp.async.bulk.wait_group 0;" ::: "memory");
}

// ---------------------------------------------------------------------------
// Kernel 1: both MLPs. 128 blocks x 256 threads; 16 rows per block.
// Thread (g,e) computes output feature e for rows 4g..4g+3.
// Triggers PDL completion at entry so agg_kernel's W-load prologue overlaps.
// ---------------------------------------------------------------------------
__global__ __launch_bounds__(256) void mlp_kernel(
    const float* __restrict__ x,
    const float* __restrict__ nw1, const float* __restrict__ nb1,
    const float* __restrict__ nw2, const float* __restrict__ nb2,
    const float* __restrict__ sw1, const float* __restrict__ sb1,
    const float* __restrict__ sw2, const float* __restrict__ sb2)
{
    cudaTriggerProgrammaticLaunchCompletion();

    __shared__ float s_w1[2][FF * FF];
    __shared__ float s_w2[2][FF * FF];
    __shared__ float s_b1[2][FF], s_b2[2][FF];
    __shared__ float sxT[FF][17];   // [k][row], padded
    __shared__ float shT[FF][17];   // hidden transposed

    int tid = threadIdx.x;
    int e = tid & 63;
    int g = tid >> 6;        // row quad 0..3

    for (int i = tid; i < FF * FF / 4; i += 256) {
        ((float4*)s_w1[0])[i] = ((const float4*)nw1)[i];
        ((float4*)s_w2[0])[i] = ((const float4*)nw2)[i];
        ((float4*)s_w1[1])[i] = ((const float4*)sw1)[i];
        ((float4*)s_w2[1])[i] = ((const float4*)sw2)[i];
    }
    if (tid < FF) {
        s_b1[0][tid] = nb1[tid];
        s_b2[0][tid] = nb2[tid];
        s_b1[1][tid] = sb1[tid];
        s_b2[1][tid] = sb2[tid];
    }

    int base = blockIdx.x * 16;     // 16 rows per block
    {
        float4 v = ((const float4*)(x + (size_t)base * FF))[tid];
        int r  = (tid * 4) / FF;    // row 0..15
        int k0 = (tid * 4) % FF;
        sxT[k0 + 0][r] = v.x;
        sxT[k0 + 1][r] = v.y;
        sxT[k0 + 2][r] = v.z;
        sxT[k0 + 3][r] = v.w;
    }
    __syncthreads();

    for (int p = 0; p < 2; p++) {   // p=0: n-MLP -> g_x1 ; p=1: s-MLP -> g_s
        float a0 = s_b1[p][e], a1 = a0, a2 = a0, a3 = a0;
        #pragma unroll
        for (int k = 0; k < FF; k++) {
            float w = s_w1[p][k * FF + e];
            a0 = fmaf(w, sxT[k][4 * g + 0], a0);
            a1 = fmaf(w, sxT[k][4 * g + 1], a1);
            a2 = fmaf(w, sxT[k][4 * g + 2], a2);
            a3 = fmaf(w, sxT[k][4 * g + 3], a3);
        }
        shT[e][4 * g + 0] = fmaxf(a0, 0.f);
        shT[e][4 * g + 1] = fmaxf(a1, 0.f);
        shT[e][4 * g + 2] = fmaxf(a2, 0.f);
        shT[e][4 * g + 3] = fmaxf(a3, 0.f);
        __syncthreads();

        float c0 = s_b2[p][e], c1 = c0, c2 = c0, c3 = c0;
        #pragma unroll
        for (int k = 0; k < FF; k++) {
            float w = s_w2[p][k * FF + e];
            c0 = fmaf(w, shT[k][4 * g + 0], c0);
            c1 = fmaf(w, shT[k][4 * g + 1], c1);
            c2 = fmaf(w, shT[k][4 * g + 2], c2);
            c3 = fmaf(w, shT[k][4 * g + 3], c3);
        }
        float* out = p ? g_s : g_x1;
        out[(size_t)(base + 4 * g + 0) * FF + e] = fmaxf(c0, 0.f);
        out[(size_t)(base + 4 * g + 1) * FF + e] = fmaxf(c1, 0.f);
        out[(size_t)(base + 4 * g + 2) * FF + e] = fmaxf(c2, 0.f);
        out[(size_t)(base + 4 * g + 3) * FF + e] = fmaxf(c3, 0.f);
        __syncthreads();    // protect shT before p=1
    }
}

// ---------------------------------------------------------------------------
// Kernel 2: fused L1-normalize + einsum + W copy + add s-MLP.
// One block per (b,i). W row streamed through a 2-stage 16KB smem ring with
// cp.async.bulk. Stage reuse is gated by cp.async.bulk.wait_group.READ
// (smem read complete) instead of the full gmem-write drain, so loads are
// never serialized behind HBM store round-trips.
// ---------------------------------------------------------------------------
__global__ __launch_bounds__(256, 6) void agg_kernel(
    const float* __restrict__ A,
    const char* __restrict__ W,
    char* __restrict__ outW,
    float* __restrict__ outX2)
{
    __shared__ float sAn[NN];
    __shared__ float4 red2[8][16];  // [warp][e4] partial sums
    __shared__ float warp_s[8];
    __shared__ float sden;
    __shared__ __align__(128) char tile[2][TILE_BYTES];
    __shared__ __align__(8) unsigned long long mbar_st[2];

    int bi = blockIdx.x;          // b*256 + i
    int b  = bi >> 8;
    int tid = threadIdx.x;

    uint32_t mb[2] = { s2u(&mbar_st[0]), s2u(&mbar_st[1]) };
    uint32_t tu[2] = { s2u(&tile[0][0]), s2u(&tile[1][0]) };

    if (tid < 2) mbar_init(mb[tid], 1);

    // L1 denom over the A row (each thread owns one j).
    float a = A[(size_t)bi * NN + tid];
    float v = fabsf(a);
    #pragma unroll
    for (int off = 16; off; off >>= 1) v += __shfl_xor_sync(0xffffffffu, v, off);
    if ((tid & 31) == 0) warp_s[tid >> 5] = v;
    __syncthreads();     // mbar init visible; warp_s ready

    const char* Wrow = W    + (size_t)bi * (NN * FF * 4);
    char*       Orow = outW + (size_t)bi * (NN * FF * 4);

    if (tid == 0) {
        float t = 0.f;
        #pragma unroll
        for (int w = 0; w < 8; w++) t += warp_s[w];
        sden = fmaxf(t, 1e-12f);
        // Prologue: kick off tile 0 load.
        mbar_expect_tx(mb[0], TILE_BYTES);
        bulk_g2s(tu[0], Wrow, TILE_BYTES, mb[0]);
    }
    __syncthreads();
    sAn[tid] = a / sden;
    __syncthreads();

    // PDL: wait for mlp's g_x1/g_s only now — the tile-0 TMA load is already
    // streaming while mlp finishes.
    cudaGridDependencySynchronize();

    const float4* x1b = ((const float4*)g_x1) + (size_t)b * (NN * 16);
    int e4 = tid & 15;    // float4 lane (features e4*4 .. e4*4+3)
    int jg = tid >> 4;    // j group 0..15 within tile

    float4 acc = make_float4(0.f, 0.f, 0.f, 0.f);

    #pragma unroll
    for (int t = 0; t < NTILES; t++) {
        int s  = t & 1;
        int ph = (t >> 1) & 1;
        mbar_wait(mb[s], ph);   // tile t resident in stage s

        if (tid == 0) {
            if (t + 1 < NTILES) {
                // Stage s^1 reusable once the store of tile t-1 has READ its
                // smem bytes (fast) — not once the gmem write drains.
                bulk_wait_read0();
                mbar_expect_tx(mb[s ^ 1], TILE_BYTES);
                bulk_g2s(tu[s ^ 1], Wrow + (size_t)(t + 1) * TILE_BYTES,
                         TILE_BYTES, mb[s ^ 1]);
            }
            // Copy-out of tile t (async proxy read of stage s).
            bulk_s2g(Orow + (size_t)t * TILE_BYTES, tu[s], TILE_BYTES);
            bulk_commit();
        }

        const float4* Wt = (const float4*)tile[s];
        #pragma unroll
        for (int k = 0; k < TILE_J / 16; k++) {
            int jl = jg + 16 * k;          // j within tile
            int j  = t * TILE_J + jl;
            float4 w   = Wt[jl * 16 + e4];
            float4 x1v = x1b[j * 16 + e4];
            float  tt  = sAn[j];
            acc.x = fmaf(tt * w.x, x1v.x, acc.x);
            acc.y = fmaf(tt * w.y, x1v.y, acc.y);
            acc.z = fmaf(tt * w.z, x1v.z, acc.z);
            acc.w = fmaf(tt * w.w, x1v.w, acc.w);
        }
        __syncthreads();   // all consumers done with stage s before reload
    }

    // Reduce over jg: lanes l and l+16 share the same e4 -> one shfl each.
    acc.x += __shfl_xor_sync(0xffffffffu, acc.x, 16);
    acc.y += __shfl_xor_sync(0xffffffffu, acc.y, 16);
    acc.z += __shfl_xor_sync(0xffffffffu, acc.z, 16);
    acc.w += __shfl_xor_sync(0xffffffffu, acc.w, 16);
    if ((tid & 31) < 16) red2[tid >> 5][e4] = acc;
    __syncthreads();

    if (tid < 16) {
        float4 r = red2[0][tid];
        #pragma unroll
        for (int w = 1; w < 8; w++) {
            float4 t = red2[w][tid];
            r.x += t.x; r.y += t.y; r.z += t.z; r.w += t.w;
        }
        float4 sv = ((const float4*)g_s)[bi * 16 + tid];
        r.x += sv.x; r.y += sv.y; r.z += sv.z; r.w += sv.w;
        ((float4*)outX2)[bi * 16 + tid] = r;
    }

    if (tid == 0) bulk_wait_all();   // full drain of W-tile stores before exit
}

// ---------------------------------------------------------------------------
extern "C" void kernel_launch(void* const* d_in, const int* in_sizes, int n_in,
                              void* d_out, int out_size)
{
    const float* A   = (const float*)d_in[0];
    const float* W   = (const float*)d_in[1];
    const float* x   = (const float*)d_in[2];
    const float* nw1 = (const float*)d_in[3];
    const float* nb1 = (const float*)d_in[4];
    const float* nw2 = (const float*)d_in[5];
    const float* nb2 = (const float*)d_in[6];
    const float* sw1 = (const float*)d_in[7];
    const float* sb1 = (const float*)d_in[8];
    const float* sw2 = (const float*)d_in[9];
    const float* sb2 = (const float*)d_in[10];

    float* outW  = (float*)d_out;            // W passthrough, 33,554,432 floats
    float* outX2 = (float*)d_out + W_ELEMS;  // x2, 131,072 floats

    // Primary: mlp (triggers PDL completion at entry).
    mlp_kernel<<<128, 256>>>(x, nw1, nb1, nw2, nb2, sw1, sb1, sw2, sb2);

    // Secondary: agg with programmatic stream serialization (W-load prologue
    // overlaps mlp; g_x1/g_s gated by cudaGridDependencySynchronize).
    cudaLaunchConfig_t cfg = {};
    cfg.gridDim = dim3(ROWS);
    cfg.blockDim = dim3(256);
    cfg.dynamicSmemBytes = 0;
    cfg.stream = 0;
    cudaLaunchAttribute attrs[1];
    attrs[0].id = cudaLaunchAttributeProgrammaticStreamSerialization;
    attrs[0].val.programmaticStreamSerializationAllowed = 1;
    cfg.attrs = attrs;
    cfg.numAttrs = 1;
    cudaLaunchKernelEx(&cfg, agg_kernel, A, (const char*)W, (char*)outW, outX2);
}